// round 7
// baseline (speedup 1.0000x reference)
#include <cuda_runtime.h>
#include <math.h>

#define E_MAX 160000
#define N_MAX 10000

// scratch (static __device__ -> allowed, no allocations)
__device__ float g_mix[(size_t)E_MAX * 256];   // per-edge radial MLP output
__device__ float g_hA[(size_t)64 * E_MAX];     // transposed activations [k][e]
__device__ float g_hB[(size_t)64 * E_MAX];
__device__ float g_y[(size_t)E_MAX * 16];      // per-edge Y_1(3),Y_2(5),Y_3(7),pad
__device__ int   g_count[N_MAX + 1];
__device__ int   g_start[N_MAX + 2];
__device__ int   g_cursor[N_MAX + 1];
__device__ int   g_esort[E_MAX];

// ---------------- packed f32x2 helpers (exact fp32, 2 FMAs / issue) ----------
__device__ __forceinline__ unsigned long long splat2(float x) {
    unsigned long long r;
    unsigned u = __float_as_uint(x);
    asm("mov.b64 %0, {%1, %1};" : "=l"(r) : "r"(u));
    return r;
}
__device__ __forceinline__ void fma2(unsigned long long& acc,
                                     unsigned long long a, unsigned long long b) {
    asm("fma.rn.f32x2 %0, %1, %2, %0;" : "+l"(acc) : "l"(a), "l"(b));
}
__device__ __forceinline__ float2 unpack2(unsigned long long v) {
    unsigned lo, hi;
    asm("mov.b64 {%0, %1}, %2;" : "=r"(lo), "=r"(hi) : "l"(v));
    return make_float2(__uint_as_float(lo), __uint_as_float(hi));
}
__device__ __forceinline__ float silu(float v) {
    return v * (1.0f / (1.0f + __expf(-v)));
}

// ---------------------------------------------------------------- zero counts
__global__ void k_zero(int n) {
    int i = blockIdx.x * blockDim.x + threadIdx.x;
    if (i <= n) g_count[i] = 0;
}

// ------------------------------------------- spherical harmonics + histogram
__global__ void k_y_hist(const float* __restrict__ vectors,
                         const int* __restrict__ receivers, int E) {
    int e = blockIdx.x * blockDim.x + threadIdx.x;
    if (e >= E) return;
    float x = vectors[3 * e + 0];
    float y = vectors[3 * e + 1];
    float z = vectors[3 * e + 2];
    float n2 = x * x + y * y + z * z;
    float inv = 1.0f / (sqrtf(n2) + 1e-12f);
    x *= inv; y *= inv; z *= inv;

    const float s3  = 1.7320508075688772f;
    const float s5  = 2.23606797749979f;
    const float s15 = 3.872983346207417f;
    const float c33 = 2.091650066335189f;
    const float c32 = 10.246950765959598f;
    const float c31 = 1.6201851746019651f;
    const float c30 = 1.3228756555322954f;

    float yv[16];
    yv[0] = s3 * y;  yv[1] = s3 * z;  yv[2] = s3 * x;
    yv[3] = s15 * x * y;
    yv[4] = s15 * y * z;
    yv[5] = 0.5f * s5 * (3.0f * z * z - 1.0f);
    yv[6] = s15 * x * z;
    yv[7] = 0.5f * s15 * (x * x - y * y);
    yv[8]  = c33 * y * (3.0f * x * x - y * y);
    yv[9]  = c32 * x * y * z;
    yv[10] = c31 * y * (5.0f * z * z - 1.0f);
    yv[11] = c30 * z * (5.0f * z * z - 3.0f);
    yv[12] = c31 * x * (5.0f * z * z - 1.0f);
    yv[13] = 0.5f * c32 * z * (x * x - y * y);
    yv[14] = c33 * x * (x * x - 3.0f * y * y);
    yv[15] = 1.0f;

    float4* o = (float4*)(g_y + (size_t)e * 16);
    o[0] = make_float4(yv[0], yv[1], yv[2], yv[3]);
    o[1] = make_float4(yv[4], yv[5], yv[6], yv[7]);
    o[2] = make_float4(yv[8], yv[9], yv[10], yv[11]);
    o[3] = make_float4(yv[12], yv[13], yv[14], yv[15]);

    atomicAdd(&g_count[receivers[e]], 1);
}

// ---------------------------------------------------------------- CSR scan
__global__ void k_scan(int n, int E) {
    __shared__ int sums[1024];
    int t = threadIdx.x;
    int chunk = (n + 1023) >> 10;
    int b = t * chunk;
    int eidx = min(b + chunk, n);
    int s = 0;
    for (int i = b; i < eidx; i++) s += g_count[i];
    sums[t] = s;
    __syncthreads();
    for (int off = 1; off < 1024; off <<= 1) {
        int v = (t >= off) ? sums[t - off] : 0;
        __syncthreads();
        sums[t] += v;
        __syncthreads();
    }
    int pre = (t > 0) ? sums[t - 1] : 0;
    for (int i = b; i < eidx; i++) {
        g_start[i]  = pre;
        g_cursor[i] = pre;
        pre += g_count[i];
    }
    if (t == 1023) g_start[n] = E;
}

// ---------------------------------------------------------------- scatter
__global__ void k_scatter(const int* __restrict__ receivers, int E) {
    int e = blockIdx.x * blockDim.x + threadIdx.x;
    if (e >= E) return;
    int p = atomicAdd(&g_cursor[receivers[e]], 1);
    g_esort[p] = e;
}

// -------------------------------------------------------------- MLP layers
// Per-layer kernels: each block caches ONLY its layer's weights (<=16.4KB smem)
// -> 8 blocks x 256 thr = 64 warps/SM. h in transposed global scratch [k][e]
// (coalesced, L2). Globals referenced from DEVICE code (addresses resolved on
// device — passing them as host-side args was R6's bug).

// layer 1: 8 -> 64, silu -> g_hA (transposed)
__global__ void __launch_bounds__(256, 8)
k_l1(const float* __restrict__ radial, const float* __restrict__ w1, int E) {
    __shared__ float ws[512];
    int tid = threadIdx.x;
    for (int i = tid; i < 512; i += 256) ws[i] = w1[i] * 0.35355339059327379f;
    __syncthreads();
    int e = blockIdx.x * 256 + tid;
    if (e >= E) return;

    const float4* rp = (const float4*)(radial + (size_t)e * 8);
    float4 a0 = __ldg(rp), a1 = __ldg(rp + 1);
    float r[8] = {a0.x, a0.y, a0.z, a0.w, a1.x, a1.y, a1.z, a1.w};

    unsigned long long acc[32];
    #pragma unroll
    for (int q = 0; q < 32; q++) acc[q] = 0ULL;
    #pragma unroll
    for (int k = 0; k < 8; k++) {
        unsigned long long a = splat2(r[k]);
        const ulonglong2* wp = (const ulonglong2*)(ws + k * 64);
        #pragma unroll
        for (int q = 0; q < 16; q++) {
            ulonglong2 w = wp[q];
            fma2(acc[2 * q],     a, w.x);
            fma2(acc[2 * q + 1], a, w.y);
        }
    }
    #pragma unroll
    for (int q = 0; q < 32; q++) {
        float2 v = unpack2(acc[q]);
        g_hA[(size_t)(2 * q)     * E_MAX + e] = silu(v.x);
        g_hA[(size_t)(2 * q + 1) * E_MAX + e] = silu(v.y);
    }
}

// common 64->64 body: in_g (transposed) -> out_g (transposed), silu
__device__ __forceinline__ void layer_body(const float* __restrict__ in_g,
                                           float* __restrict__ out_g,
                                           const float* __restrict__ Wg, int E) {
    __shared__ float ws[4096];
    int tid = threadIdx.x;
    for (int i = tid; i < 4096; i += 256) ws[i] = Wg[i] * 0.125f;
    __syncthreads();
    int e = blockIdx.x * 256 + tid;
    if (e >= E) return;

    unsigned long long acc[32];
    #pragma unroll
    for (int q = 0; q < 32; q++) acc[q] = 0ULL;
    #pragma unroll 4
    for (int k = 0; k < 64; k++) {
        unsigned long long a = splat2(__ldg(in_g + (size_t)k * E_MAX + e));
        const ulonglong2* wp = (const ulonglong2*)(ws + k * 64);
        #pragma unroll
        for (int q = 0; q < 16; q++) {
            ulonglong2 w = wp[q];
            fma2(acc[2 * q],     a, w.x);
            fma2(acc[2 * q + 1], a, w.y);
        }
    }
    #pragma unroll
    for (int q = 0; q < 32; q++) {
        float2 v = unpack2(acc[q]);
        out_g[(size_t)(2 * q)     * E_MAX + e] = silu(v.x);
        out_g[(size_t)(2 * q + 1) * E_MAX + e] = silu(v.y);
    }
}

__global__ void __launch_bounds__(256, 8)
k_l2(const float* __restrict__ w2, int E) { layer_body(g_hA, g_hB, w2, E); }

__global__ void __launch_bounds__(256, 8)
k_l3(const float* __restrict__ w3, int E) { layer_body(g_hB, g_hA, w3, E); }

// layer 4: 64 -> 256, no activation; blockIdx.y picks a 64-wide j-chunk,
// block caches the 16KB w4 slice. Output g_mix row-major per edge.
__global__ void __launch_bounds__(256, 8)
k_l4(const float* __restrict__ w4, int E) {
    __shared__ float ws[4096];
    int tid = threadIdx.x;
    int j0 = blockIdx.y * 64;
    for (int i = tid; i < 4096; i += 256) {
        int k = i >> 6, j = i & 63;
        ws[i] = w4[k * 256 + j0 + j] * 0.125f;
    }
    __syncthreads();
    int e = blockIdx.x * 256 + tid;
    if (e >= E) return;

    unsigned long long acc[32];
    #pragma unroll
    for (int q = 0; q < 32; q++) acc[q] = 0ULL;
    #pragma unroll 4
    for (int k = 0; k < 64; k++) {
        unsigned long long a = splat2(__ldg(g_hA + (size_t)k * E_MAX + e));
        const ulonglong2* wp = (const ulonglong2*)(ws + k * 64);
        #pragma unroll
        for (int q = 0; q < 16; q++) {
            ulonglong2 w = wp[q];
            fma2(acc[2 * q],     a, w.x);
            fma2(acc[2 * q + 1], a, w.y);
        }
    }
    // packed u64 pairs are exactly two consecutive floats -> direct stores
    ulonglong2* op = (ulonglong2*)(g_mix + (size_t)e * 256 + j0);
    #pragma unroll
    for (int q = 0; q < 16; q++)
        op[q] = make_ulonglong2(acc[2 * q], acc[2 * q + 1]);
}

// --------------------------------------------------- gather-side reduction
__global__ void __launch_bounds__(256)
k_out(const float* __restrict__ node_feats, const int* __restrict__ senders,
      float* __restrict__ out, int N) {
    __shared__ float red[8 * 1024];
    int node = blockIdx.x;
    int tid = threadIdx.x;
    int w = tid >> 5, lane = tid & 31;
    int beg = g_start[node], end = g_start[node + 1];

    float acc[32];
    #pragma unroll
    for (int i = 0; i < 32; i++) acc[i] = 0.0f;

    for (int p = beg + w; p < end; p += 8) {
        int e = g_esort[p];
        int snd = senders[e];
        const float* mixp = g_mix + (size_t)e * 256;
        const float4* yp = (const float4*)(g_y + (size_t)e * 16);
        float4 ya = __ldg(yp), yb = __ldg(yp + 1), yc = __ldg(yp + 2), yd = __ldg(yp + 3);
        float yv[15] = {ya.x, ya.y, ya.z, ya.w, yb.x, yb.y, yb.z, yb.w,
                        yc.x, yc.y, yc.z, yc.w, yd.x, yd.y, yd.z};
        #pragma unroll
        for (int h = 0; h < 2; h++) {
            int c = lane + 32 * h;
            float s   = __ldg(node_feats + (size_t)snd * 64 + c);
            float sm0 = s * __ldg(mixp + c);
            float sm1 = s * __ldg(mixp + 64 + c);
            float sm2 = s * __ldg(mixp + 128 + c);
            float sm3 = s * __ldg(mixp + 192 + c);
            float* a = acc + 16 * h;
            a[0] += sm0;
            a[1] = fmaf(sm1, yv[0], a[1]);
            a[2] = fmaf(sm1, yv[1], a[2]);
            a[3] = fmaf(sm1, yv[2], a[3]);
            #pragma unroll
            for (int m = 0; m < 5; m++) a[4 + m] = fmaf(sm2, yv[3 + m], a[4 + m]);
            #pragma unroll
            for (int m = 0; m < 7; m++) a[9 + m] = fmaf(sm3, yv[8 + m], a[9 + m]);
        }
    }

    float* rw = red + w * 1024;
    #pragma unroll
    for (int h = 0; h < 2; h++) {
        int c = lane + 32 * h;
        float* a = acc + 16 * h;
        rw[c] = a[0];
        rw[64 + c * 3 + 0] = a[1];
        rw[64 + c * 3 + 1] = a[2];
        rw[64 + c * 3 + 2] = a[3];
        #pragma unroll
        for (int m = 0; m < 5; m++) rw[256 + c * 5 + m] = a[4 + m];
        #pragma unroll
        for (int m = 0; m < 7; m++) rw[576 + c * 7 + m] = a[9 + m];
    }
    __syncthreads();

    float* outp = out + (size_t)node * 1024;
    #pragma unroll
    for (int i = 0; i < 4; i++) {
        int o = tid + 256 * i;
        float sum = 0.0f;
        #pragma unroll
        for (int ww = 0; ww < 8; ww++) sum += red[ww * 1024 + o];
        outp[o] = sum * 0.25f;   // 1/sqrt(16)
    }
}

// ---------------------------------------------------------------- launcher
extern "C" void kernel_launch(void* const* d_in, const int* in_sizes, int n_in,
                              void* d_out, int out_size) {
    const float* vectors    = (const float*)d_in[0];
    const float* node_feats = (const float*)d_in[1];
    const float* radial     = (const float*)d_in[2];
    const float* w1         = (const float*)d_in[3];
    const float* w2         = (const float*)d_in[4];
    const float* w3         = (const float*)d_in[5];
    const float* w4         = (const float*)d_in[6];
    const int*   senders    = (const int*)d_in[7];
    const int*   receivers  = (const int*)d_in[8];

    int E = in_sizes[7];
    int N = in_sizes[1] / 64;

    int gE = (E + 255) / 256;
    k_zero<<<(N + 1 + 255) / 256, 256>>>(N);
    k_y_hist<<<gE, 256>>>(vectors, receivers, E);
    k_scan<<<1, 1024>>>(N, E);
    k_l1<<<gE, 256>>>(radial, w1, E);
    k_l2<<<gE, 256>>>(w2, E);
    k_l3<<<gE, 256>>>(w3, E);
    k_l4<<<dim3(gE, 4), 256>>>(w4, E);
    k_scatter<<<gE, 256>>>(receivers, E);
    k_out<<<N, 256>>>(node_feats, senders, (float*)d_out, N);
}

// round 8
// speedup vs baseline: 7.9311x; 7.9311x over previous
#include <cuda_runtime.h>
#include <math.h>

#define E_MAX 160000
#define N_MAX 10000

// scratch (static __device__ -> allowed, no allocations)
__device__ float g_mix[(size_t)E_MAX * 256];   // per-edge radial MLP output
__device__ float g_hA[(size_t)64 * E_MAX];     // transposed activations [k][e]
__device__ float g_hB[(size_t)64 * E_MAX];
__device__ float g_y[(size_t)E_MAX * 16];      // per-edge Y_1(3),Y_2(5),Y_3(7),pad
__device__ int   g_count[N_MAX + 1];
__device__ int   g_start[N_MAX + 2];
__device__ int   g_cursor[N_MAX + 1];
__device__ int   g_esort[E_MAX];

// ---------------- packed f32x2 helpers (exact fp32, 2 FMAs / issue) ----------
__device__ __forceinline__ unsigned long long splat2(float x) {
    unsigned long long r;
    unsigned u = __float_as_uint(x);
    asm("mov.b64 %0, {%1, %1};" : "=l"(r) : "r"(u));
    return r;
}
__device__ __forceinline__ void fma2(unsigned long long& acc,
                                     unsigned long long a, unsigned long long b) {
    asm("fma.rn.f32x2 %0, %1, %2, %0;" : "+l"(acc) : "l"(a), "l"(b));
}
__device__ __forceinline__ float2 unpack2(unsigned long long v) {
    unsigned lo, hi;
    asm("mov.b64 {%0, %1}, %2;" : "=r"(lo), "=r"(hi) : "l"(v));
    return make_float2(__uint_as_float(lo), __uint_as_float(hi));
}
__device__ __forceinline__ float silu(float v) {
    return v * (1.0f / (1.0f + __expf(-v)));
}

// ---------------------------------------------------------------- zero counts
__global__ void k_zero(int n) {
    int i = blockIdx.x * blockDim.x + threadIdx.x;
    if (i <= n) g_count[i] = 0;
}

// ------------------------------------------- spherical harmonics + histogram
__global__ void k_y_hist(const float* __restrict__ vectors,
                         const int* __restrict__ receivers, int E) {
    int e = blockIdx.x * blockDim.x + threadIdx.x;
    if (e >= E) return;
    float x = vectors[3 * e + 0];
    float y = vectors[3 * e + 1];
    float z = vectors[3 * e + 2];
    float n2 = x * x + y * y + z * z;
    float inv = 1.0f / (sqrtf(n2) + 1e-12f);
    x *= inv; y *= inv; z *= inv;

    const float s3  = 1.7320508075688772f;
    const float s5  = 2.23606797749979f;
    const float s15 = 3.872983346207417f;
    const float c33 = 2.091650066335189f;
    const float c32 = 10.246950765959598f;
    const float c31 = 1.6201851746019651f;
    const float c30 = 1.3228756555322954f;

    float yv[16];
    yv[0] = s3 * y;  yv[1] = s3 * z;  yv[2] = s3 * x;
    yv[3] = s15 * x * y;
    yv[4] = s15 * y * z;
    yv[5] = 0.5f * s5 * (3.0f * z * z - 1.0f);
    yv[6] = s15 * x * z;
    yv[7] = 0.5f * s15 * (x * x - y * y);
    yv[8]  = c33 * y * (3.0f * x * x - y * y);
    yv[9]  = c32 * x * y * z;
    yv[10] = c31 * y * (5.0f * z * z - 1.0f);
    yv[11] = c30 * z * (5.0f * z * z - 3.0f);
    yv[12] = c31 * x * (5.0f * z * z - 1.0f);
    yv[13] = 0.5f * c32 * z * (x * x - y * y);
    yv[14] = c33 * x * (x * x - 3.0f * y * y);
    yv[15] = 1.0f;

    float4* o = (float4*)(g_y + (size_t)e * 16);
    o[0] = make_float4(yv[0], yv[1], yv[2], yv[3]);
    o[1] = make_float4(yv[4], yv[5], yv[6], yv[7]);
    o[2] = make_float4(yv[8], yv[9], yv[10], yv[11]);
    o[3] = make_float4(yv[12], yv[13], yv[14], yv[15]);

    atomicAdd(&g_count[receivers[e]], 1);
}

// ---------------------------------------------------------------- CSR scan
__global__ void k_scan(int n, int E) {
    __shared__ int sums[1024];
    int t = threadIdx.x;
    int chunk = (n + 1023) >> 10;
    int b = t * chunk;
    int eidx = min(b + chunk, n);
    int s = 0;
    for (int i = b; i < eidx; i++) s += g_count[i];
    sums[t] = s;
    __syncthreads();
    for (int off = 1; off < 1024; off <<= 1) {
        int v = (t >= off) ? sums[t - off] : 0;
        __syncthreads();
        sums[t] += v;
        __syncthreads();
    }
    int pre = (t > 0) ? sums[t - 1] : 0;
    for (int i = b; i < eidx; i++) {
        g_start[i]  = pre;
        g_cursor[i] = pre;
        pre += g_count[i];
    }
    if (t == 1023) g_start[n] = E;
}

// ---------------------------------------------------------------- scatter
__global__ void k_scatter(const int* __restrict__ receivers, int E) {
    int e = blockIdx.x * blockDim.x + threadIdx.x;
    if (e >= E) return;
    int p = atomicAdd(&g_cursor[receivers[e]], 1);
    g_esort[p] = e;
}

// -------------------------------------------------------------- MLP layers
// Per-layer kernels, J=32 output slice per block (blockIdx.y), 8KB weight
// smem, __launch_bounds__(256,4) -> 64-reg cap, 32 warps/SM, NO spills
// (acc = 16 u64 = 32 regs). h in transposed global scratch [k][e], coalesced.

// core: acc[0..15] (u64) = sum_k h[k] * ws[k*32 .. k*32+31]
__device__ __forceinline__ void pass32(const float* __restrict__ in_g, int e,
                                       const float* __restrict__ ws,
                                       unsigned long long* __restrict__ acc) {
    #pragma unroll
    for (int q = 0; q < 16; q++) acc[q] = 0ULL;
    #pragma unroll 4
    for (int k = 0; k < 64; k++) {
        unsigned long long a = splat2(__ldg(in_g + (size_t)k * E_MAX + e));
        const ulonglong2* wp = (const ulonglong2*)(ws + k * 32);
        #pragma unroll
        for (int q = 0; q < 8; q++) {
            ulonglong2 w = wp[q];
            fma2(acc[2 * q],     a, w.x);
            fma2(acc[2 * q + 1], a, w.y);
        }
    }
}

__device__ __forceinline__ void silu_store32(float* __restrict__ out_g, int j0, int e,
                                             const unsigned long long* __restrict__ acc) {
    #pragma unroll
    for (int q = 0; q < 16; q++) {
        float2 v = unpack2(acc[q]);
        out_g[(size_t)(j0 + 2 * q)     * E_MAX + e] = silu(v.x);
        out_g[(size_t)(j0 + 2 * q + 1) * E_MAX + e] = silu(v.y);
    }
}

// layer 1: 8 -> 64 (j-half per blockIdx.y), silu -> g_hA
__global__ void __launch_bounds__(256, 4)
k_l1(const float* __restrict__ radial, const float* __restrict__ w1, int E) {
    __shared__ float ws[8 * 32];
    int tid = threadIdx.x;
    int j0 = blockIdx.y * 32;
    if (tid < 256) {
        int k = tid >> 5, j = tid & 31;
        ws[tid] = w1[k * 64 + j0 + j] * 0.35355339059327379f;
    }
    __syncthreads();
    int e = blockIdx.x * 256 + tid;
    if (e >= E) return;

    const float4* rp = (const float4*)(radial + (size_t)e * 8);
    float4 a0 = __ldg(rp), a1 = __ldg(rp + 1);
    float r[8] = {a0.x, a0.y, a0.z, a0.w, a1.x, a1.y, a1.z, a1.w};

    unsigned long long acc[16];
    #pragma unroll
    for (int q = 0; q < 16; q++) acc[q] = 0ULL;
    #pragma unroll
    for (int k = 0; k < 8; k++) {
        unsigned long long a = splat2(r[k]);
        const ulonglong2* wp = (const ulonglong2*)(ws + k * 32);
        #pragma unroll
        for (int q = 0; q < 8; q++) {
            ulonglong2 w = wp[q];
            fma2(acc[2 * q],     a, w.x);
            fma2(acc[2 * q + 1], a, w.y);
        }
    }
    silu_store32(g_hA, j0, e, acc);
}

// common 64 -> 32-slice body (silu)
__device__ __forceinline__ void layer_body(const float* __restrict__ in_g,
                                           float* __restrict__ out_g,
                                           const float* __restrict__ Wg, int E) {
    __shared__ float ws[64 * 32];
    int tid = threadIdx.x;
    int j0 = blockIdx.y * 32;
    for (int i = tid; i < 64 * 32; i += 256) {
        int k = i >> 5, j = i & 31;
        ws[i] = Wg[k * 64 + j0 + j] * 0.125f;
    }
    __syncthreads();
    int e = blockIdx.x * 256 + tid;
    if (e >= E) return;

    unsigned long long acc[16];
    pass32(in_g, e, ws, acc);
    silu_store32(out_g, j0, e, acc);
}

__global__ void __launch_bounds__(256, 4)
k_l2(const float* __restrict__ w2, int E) { layer_body(g_hA, g_hB, w2, E); }

__global__ void __launch_bounds__(256, 4)
k_l3(const float* __restrict__ w3, int E) { layer_body(g_hB, g_hA, w3, E); }

// layer 4: 64 -> 256, blockIdx.y picks a 32-wide j-slice (8 of them),
// no activation; g_mix row-major per edge.
__global__ void __launch_bounds__(256, 4)
k_l4(const float* __restrict__ w4, int E) {
    __shared__ float ws[64 * 32];
    int tid = threadIdx.x;
    int j0 = blockIdx.y * 32;
    for (int i = tid; i < 64 * 32; i += 256) {
        int k = i >> 5, j = i & 31;
        ws[i] = w4[k * 256 + j0 + j] * 0.125f;
    }
    __syncthreads();
    int e = blockIdx.x * 256 + tid;
    if (e >= E) return;

    unsigned long long acc[16];
    pass32(g_hA, e, ws, acc);
    // packed u64 pairs are exactly two consecutive floats -> direct stores
    ulonglong2* op = (ulonglong2*)(g_mix + (size_t)e * 256 + j0);
    #pragma unroll
    for (int q = 0; q < 8; q++)
        op[q] = make_ulonglong2(acc[2 * q], acc[2 * q + 1]);
}

// --------------------------------------------------- gather-side reduction
__global__ void __launch_bounds__(256)
k_out(const float* __restrict__ node_feats, const int* __restrict__ senders,
      float* __restrict__ out, int N) {
    __shared__ float red[8 * 1024];
    int node = blockIdx.x;
    int tid = threadIdx.x;
    int w = tid >> 5, lane = tid & 31;
    int beg = g_start[node], end = g_start[node + 1];

    float acc[32];
    #pragma unroll
    for (int i = 0; i < 32; i++) acc[i] = 0.0f;

    for (int p = beg + w; p < end; p += 8) {
        int e = g_esort[p];
        int snd = senders[e];
        const float* mixp = g_mix + (size_t)e * 256;
        const float4* yp = (const float4*)(g_y + (size_t)e * 16);
        float4 ya = __ldg(yp), yb = __ldg(yp + 1), yc = __ldg(yp + 2), yd = __ldg(yp + 3);
        float yv[15] = {ya.x, ya.y, ya.z, ya.w, yb.x, yb.y, yb.z, yb.w,
                        yc.x, yc.y, yc.z, yc.w, yd.x, yd.y, yd.z};
        #pragma unroll
        for (int h = 0; h < 2; h++) {
            int c = lane + 32 * h;
            float s   = __ldg(node_feats + (size_t)snd * 64 + c);
            float sm0 = s * __ldg(mixp + c);
            float sm1 = s * __ldg(mixp + 64 + c);
            float sm2 = s * __ldg(mixp + 128 + c);
            float sm3 = s * __ldg(mixp + 192 + c);
            float* a = acc + 16 * h;
            a[0] += sm0;
            a[1] = fmaf(sm1, yv[0], a[1]);
            a[2] = fmaf(sm1, yv[1], a[2]);
            a[3] = fmaf(sm1, yv[2], a[3]);
            #pragma unroll
            for (int m = 0; m < 5; m++) a[4 + m] = fmaf(sm2, yv[3 + m], a[4 + m]);
            #pragma unroll
            for (int m = 0; m < 7; m++) a[9 + m] = fmaf(sm3, yv[8 + m], a[9 + m]);
        }
    }

    float* rw = red + w * 1024;
    #pragma unroll
    for (int h = 0; h < 2; h++) {
        int c = lane + 32 * h;
        float* a = acc + 16 * h;
        rw[c] = a[0];
        rw[64 + c * 3 + 0] = a[1];
        rw[64 + c * 3 + 1] = a[2];
        rw[64 + c * 3 + 2] = a[3];
        #pragma unroll
        for (int m = 0; m < 5; m++) rw[256 + c * 5 + m] = a[4 + m];
        #pragma unroll
        for (int m = 0; m < 7; m++) rw[576 + c * 7 + m] = a[9 + m];
    }
    __syncthreads();

    float* outp = out + (size_t)node * 1024;
    #pragma unroll
    for (int i = 0; i < 4; i++) {
        int o = tid + 256 * i;
        float sum = 0.0f;
        #pragma unroll
        for (int ww = 0; ww < 8; ww++) sum += red[ww * 1024 + o];
        outp[o] = sum * 0.25f;   // 1/sqrt(16)
    }
}

// ---------------------------------------------------------------- launcher
extern "C" void kernel_launch(void* const* d_in, const int* in_sizes, int n_in,
                              void* d_out, int out_size) {
    const float* vectors    = (const float*)d_in[0];
    const float* node_feats = (const float*)d_in[1];
    const float* radial     = (const float*)d_in[2];
    const float* w1         = (const float*)d_in[3];
    const float* w2         = (const float*)d_in[4];
    const float* w3         = (const float*)d_in[5];
    const float* w4         = (const float*)d_in[6];
    const int*   senders    = (const int*)d_in[7];
    const int*   receivers  = (const int*)d_in[8];

    int E = in_sizes[7];
    int N = in_sizes[1] / 64;

    int gE = (E + 255) / 256;
    k_zero<<<(N + 1 + 255) / 256, 256>>>(N);
    k_y_hist<<<gE, 256>>>(vectors, receivers, E);
    k_scan<<<1, 1024>>>(N, E);
    k_l1<<<dim3(gE, 2), 256>>>(radial, w1, E);
    k_l2<<<dim3(gE, 2), 256>>>(w2, E);
    k_l3<<<dim3(gE, 2), 256>>>(w3, E);
    k_l4<<<dim3(gE, 8), 256>>>(w4, E);
    k_scatter<<<gE, 256>>>(receivers, E);
    k_out<<<N, 256>>>(node_feats, senders, (float*)d_out, N);
}